// round 17
// baseline (speedup 1.0000x reference)
#include <cuda_runtime.h>
#include <math.h>

#define NBOX   4096
#define RPB    128                      // pred rows per pair block
#define CHUNK  128                      // targets per pair block
#define NBLK   1024                     // 32x32 pair blocks
#define NCELL  64                       // 8x8 spatial cells (100px), morton order

// Scratch (device globals: no allocation allowed in kernel_launch)
__device__ int    g_cnt[NCELL];         // pred per-cell counts (zeroed by pair tail)
__device__ float4 g_sP4[NBOX];          // spatially sorted preds
__device__ int    g_sPi[NBOX];          // original indices
__device__ unsigned long long g_best[NBOX]; // packed (ratio_bits<<32 | ~argOrig); 0 = none
__device__ float  g_rbS[NBLK];
__device__ int    g_rbC[NBLK];
__device__ unsigned int g_ticket;       // global pair ticket (reset by pair tail)

__device__ __forceinline__ int cellOf(float x, float y) {
    int cx = (int)(x * 0.01f); cx = cx < 0 ? 0 : (cx > 7 ? 7 : cx);
    int cy = (int)(y * 0.01f); cy = cy < 0 ? 0 : (cy > 7 ? 7 : cy);
    return (cx & 1) | ((cy & 1) << 1) | ((cx & 2) << 1) |
           ((cy & 2) << 2) | ((cx & 4) << 2) | ((cy & 4) << 3);
}

// ---------------------------------------------------------------------------
// Kernel 0: rank + scatter for PREDS ONLY (R16-identical).
// One 4-CTA cluster x 1024 threads; parallel smem prefix scan.
// ---------------------------------------------------------------------------
__global__ __launch_bounds__(1024) __cluster_dims__(4, 1, 1)
void sort_kernel(const float4* __restrict__ pred4)
{
    const int tid  = threadIdx.x;
    const int idx  = blockIdx.x * 1024 + tid;

    __shared__ int sh[NCELL], sbase[NCELL], sscan[NCELL], sfin[NCELL];
    if (tid < NCELL) sh[tid] = 0;
    __syncthreads();

    const float4 v = pred4[idx];
    const int cell = cellOf(v.x, v.y);
    const int lr   = atomicAdd(&sh[cell], 1);
    __syncthreads();
    if (tid < NCELL) sbase[tid] = atomicAdd(&g_cnt[tid], sh[tid]);
    __syncthreads();
    const int rank = sbase[cell] + lr;

    // ---- cluster barrier: all 4 blocks have added their counts ----
    __threadfence();
    asm volatile("barrier.cluster.arrive.aligned;" ::: "memory");
    asm volatile("barrier.cluster.wait.aligned;" ::: "memory");

    if (tid < NCELL) { sfin[tid] = g_cnt[tid]; sscan[tid] = sfin[tid]; }
    __syncthreads();
    #pragma unroll
    for (int o = 1; o < NCELL; o <<= 1) {
        int add = 0;
        if (tid < NCELL && tid >= o) add = sscan[tid - o];
        __syncthreads();
        if (tid < NCELL) sscan[tid] += add;
        __syncthreads();
    }

    const int pos = sscan[cell] - sfin[cell] + rank;   // exclusive + rank
    g_sP4[pos] = v;
    g_sPi[pos] = idx;
}

// ---------------------------------------------------------------------------
// Kernel 1: pair sweep with target compaction + fused finalize tail.
// The 1024th block (global ticket) performs the entire combine: sl1, RepGT
// finalize (32 rows/thread), RepBox partial reduce, broadcast, scratch reset.
// ---------------------------------------------------------------------------
__global__ __launch_bounds__(RPB)
void pair_kernel(const float4* __restrict__ pred4,
                 const float4* __restrict__ tgt4,
                 float* __restrict__ out)
{
    const int tid = threadIdx.x;
    const int bx = blockIdx.x, by = blockIdx.y;
    const int b  = bx * 32 + by;
    const int lane = tid & 31, wrp = tid >> 5;

    __shared__ float4 sT2[CHUNK];   // compacted targets {x0, y0, x2+1, y2+1}
    __shared__ float2 sAJ2[CHUNK];  // compacted (area+1conv, orig idx bits)
    __shared__ float4 sPB[4];       // per-warp pred bbox
    __shared__ int sCnt[4], sBase[4], sN;
    __shared__ unsigned int sGlobLast;

    // --- own pred row + warp bbox ---
    const int r = bx * RPB + tid;
    float4 p = g_sP4[r];
    const int iO = g_sPi[r];
    const float areaP = (p.z - p.x + 1.0f) * (p.w - p.y + 1.0f);
    p.z += 1.0f; p.w += 1.0f;

    {
        float mnx = p.x, mxx = p.z, mny = p.y, mxy = p.w;
        #pragma unroll
        for (int o = 16; o > 0; o >>= 1) {
            mnx = fminf(mnx, __shfl_xor_sync(0xffffffffu, mnx, o));
            mxx = fmaxf(mxx, __shfl_xor_sync(0xffffffffu, mxx, o));
            mny = fminf(mny, __shfl_xor_sync(0xffffffffu, mny, o));
            mxy = fmaxf(mxy, __shfl_xor_sync(0xffffffffu, mxy, o));
        }
        if (lane == 0) sPB[wrp] = make_float4(mnx, mxx, mny, mxy);
    }
    __syncthreads();

    // block pred bbox (uniform)
    const float pmnx = fminf(fminf(sPB[0].x, sPB[1].x), fminf(sPB[2].x, sPB[3].x));
    const float pmxx = fmaxf(fmaxf(sPB[0].y, sPB[1].y), fmaxf(sPB[2].y, sPB[3].y));
    const float pmny = fminf(fminf(sPB[0].z, sPB[1].z), fminf(sPB[2].z, sPB[3].z));
    const float pmxy = fmaxf(fmaxf(sPB[0].w, sPB[1].w), fmaxf(sPB[2].w, sPB[3].w));

    // --- load my target (unsorted input), test vs block bbox, compaction ---
    {
        const int jO = by * CHUNK + tid;        // original index == position
        float4 t = tgt4[jO];
        const float a = (t.z - t.x + 1.0f) * (t.w - t.y + 1.0f);
        t.z += 1.0f; t.w += 1.0f;
        const bool pass = (pmxx > t.x) && (t.z > pmnx) &&
                          (pmxy > t.y) && (t.w > pmny);
        const unsigned m = __ballot_sync(0xffffffffu, pass);
        if (lane == 0) sCnt[wrp] = __popc(m);
        __syncthreads();
        if (tid == 0) {
            int acc = 0;
            #pragma unroll
            for (int w = 0; w < 4; ++w) { sBase[w] = acc; acc += sCnt[w]; }
            sN = acc;
        }
        __syncthreads();
        if (pass) {
            const int pos = sBase[wrp] + __popc(m & ((1u << lane) - 1u));
            sT2[pos]  = t;
            sAJ2[pos] = make_float2(a, __int_as_float(jO));
        }
    }
    __syncthreads();

    const int nAct = sN;
    {
        float bI = 0.0f, bU = 1.0f;
        int   bA = 0;
        float rbS = 0.0f;
        int   rbC = 0;

        #pragma unroll 4
        for (int k = 0; k < nAct; ++k) {
            const float4 t  = sT2[k];
            const float2 aj = sAJ2[k];
            float iw = fminf(p.z, t.z) - fmaxf(p.x, t.x);
            float ih = fminf(p.w, t.w) - fmaxf(p.y, t.y);
            iw = fmaxf(iw, 0.0f);
            ih = fmaxf(ih, 0.0f);
            const float inter = iw * ih;
            const float ua    = areaP + aj.x - inter;
            const int   jO    = __float_as_int(aj.y);
            if ((jO != iO) && (inter * bU > bI * ua)) {
                bI = inter; bU = ua; bA = jO;
            }
            if ((jO < iO) && (inter > 0.0f)) {
                rbS += __fdividef(inter, ua);
                rbC += 1;
            }
        }

        if (bI > 0.0f) {
            const float ratio = bI / bU;
            const unsigned long long packed =
                ((unsigned long long)__float_as_uint(ratio) << 32) |
                (unsigned long long)(0xFFFFFFFFu - (unsigned)bA);
            atomicMax(&g_best[iO], packed);    // indexed by ORIGINAL row
        }

        #pragma unroll
        for (int o = 16; o > 0; o >>= 1) {
            rbS += __shfl_down_sync(0xffffffffu, rbS, o);
            rbC += __shfl_down_sync(0xffffffffu, rbC, o);
        }
        __shared__ float wS[RPB / 32];
        __shared__ int   wC[RPB / 32];
        if (lane == 0) { wS[wrp] = rbS; wC[wrp] = rbC; }
        __syncthreads();
        if (tid == 0) {
            float s = 0.0f; int c = 0;
            #pragma unroll
            for (int w = 0; w < RPB / 32; ++w) { s += wS[w]; c += wC[w]; }
            g_rbS[b] = s;
            g_rbC[b] = c;
        }
    }

    // ---- global ticket: last of 1024 blocks runs the full finalize ----
    __syncthreads();
    if (tid == 0) {
        __threadfence();
        sGlobLast = (atomicAdd(&g_ticket, 1u) == NBLK - 1u) ? 1u : 0u;
    }
    __syncthreads();
    if (sGlobLast == 0u) return;

    // ======================= finalize tail (one block) ======================
    {
        double sl = 0.0, sg = 0.0;
        int cg = 0;

        #pragma unroll 4
        for (int q = 0; q < NBOX / RPB; ++q) {      // 32 rows per thread
            const int row = q * RPB + tid;
            const float4 pe = pred4[row];
            const float4 te = tgt4[row];
            float slf = 0.0f, d;
            d = fabsf(pe.x - te.x); slf += (d < 1.0f) ? 0.5f * d * d : d - 0.5f;
            d = fabsf(pe.y - te.y); slf += (d < 1.0f) ? 0.5f * d * d : d - 0.5f;
            d = fabsf(pe.z - te.z); slf += (d < 1.0f) ? 0.5f * d * d : d - 0.5f;
            d = fabsf(pe.w - te.w); slf += (d < 1.0f) ? 0.5f * d * d : d - 0.5f;
            sl += (double)slf;

            const unsigned long long packed = __ldcg(&g_best[row]);
            g_best[row] = 0ull;                     // reset for next replay
            if (packed != 0ull) {                   // max_ov > 0 mask
                const int bA2 = (int)(0xFFFFFFFFu -
                                      (unsigned)(packed & 0xFFFFFFFFull));
                const float4 g = tgt4[bA2];
                const float iw = fmaxf(fminf(pe.z, g.z) - fmaxf(pe.x, g.x), 0.0f);
                const float ih = fmaxf(fminf(pe.w, g.w) - fmaxf(pe.y, g.y), 0.0f);
                const float garea = (g.z - g.x) * (g.w - g.y);
                const float iog = iw * ih / garea;  // no +1 convention for IoG
                float v;
                if (iog > 0.9f) {
                    v = (iog - 0.9f) / (1.0f - 0.9f) + 2.3025851f; // -log1p(-0.9)
                } else {
                    const float xc = fminf(fmaxf(iog, 0.0f), 1.0f - 1e-6f);
                    v = -log1pf(-xc);
                }
                sg += (double)v;
                cg += 1;
            }
        }

        // RepBox partials: 8 per thread (fixed order)
        double rb = 0.0;
        long long cb = 0;
        #pragma unroll
        for (int q = 0; q < NBLK / RPB; ++q) {
            const int bb = q * RPB + tid;
            rb += (double)__ldcg(&g_rbS[bb]);
            cb += (long long)__ldcg(&g_rbC[bb]);
        }

        // scratch reset for next graph replay
        if (tid < NCELL) g_cnt[tid] = 0;
        if (tid == 0) g_ticket = 0u;

        // deterministic block reduction
        #pragma unroll
        for (int o = 16; o > 0; o >>= 1) {
            sl += __shfl_down_sync(0xffffffffu, sl, o);
            sg += __shfl_down_sync(0xffffffffu, sg, o);
            rb += __shfl_down_sync(0xffffffffu, rb, o);
            cg += __shfl_down_sync(0xffffffffu, cg, o);
            cb += __shfl_down_sync(0xffffffffu, cb, o);
        }
        __shared__ double hL[4], hG[4], hR[4];
        __shared__ int hC[4];
        __shared__ long long hB[4];
        __shared__ float sScalar;
        if (lane == 0) { hL[wrp] = sl; hG[wrp] = sg; hR[wrp] = rb;
                         hC[wrp] = cg; hB[wrp] = cb; }
        __syncthreads();
        if (tid == 0) {
            double al = 0.0, ag = 0.0, ar = 0.0;
            int ac = 0; long long ab = 0;
            #pragma unroll
            for (int w = 0; w < 4; ++w) {
                al += hL[w]; ag += hG[w]; ar += hR[w]; ac += hC[w]; ab += hB[w];
            }
            const float sl1    = (float)(al / (double)(NBOX * 4));
            const float repgt  = (ac > 0) ? (float)(ag / (double)ac) : 0.0f;
            const float repbox = (ab > 0) ? (float)(ar / (double)ab) : 0.0f;
            sScalar = sl1 + repgt + repbox;
        }
        __syncthreads();

        const float s = sScalar;
        float4* out4 = (float4*)out;
        const float4 v = make_float4(s, s, s, s);
        #pragma unroll
        for (int q = 0; q < NBOX / 4 / RPB; ++q)    // 8 float4 per thread
            out4[q * RPB + tid] = v;
    }
}

// ---------------------------------------------------------------------------
extern "C" void kernel_launch(void* const* d_in, const int* in_sizes, int n_in,
                              void* d_out, int out_size)
{
    const float* pred = (const float*)d_in[0];
    const float* tgt  = (const float*)d_in[1];
    float* out = (float*)d_out;

    sort_kernel<<<4, 1024>>>((const float4*)pred);
    dim3 grid(32, 32);
    pair_kernel<<<grid, RPB>>>((const float4*)pred, (const float4*)tgt, out);
}